// round 5
// baseline (speedup 1.0000x reference)
#include <cuda_runtime.h>

// Problem constants
#define N_ROWS 65536   // B*H*W = 64*32*32
#define DIM    256     // D
#define KCB    1024    // K

#define OFF_PERP  16777216
#define OFF_LOSS  16777217
#define OFF_CB    16777218

// packed f32x2 FMA: d = a*b + c, lane-wise fp32 (bit-identical to fmaf per lane)
#define FMA_F32X2(d, a, b, c) \
    asm("fma.rn.f32x2 %0, %1, %2, %3;" : "=l"(d) : "l"(a), "l"(b), "l"(c))

// ---------------- scratch (device globals; no allocation allowed) -----------
__device__ float g_cbT[KCB * DIM];      // codebook transposed [K, D]
__device__ float g_cnorm[KCB];          // |e_k|^2
__device__ float g_xnorm[N_ROWS];       // |x_n|^2
__device__ float g_pminval[N_ROWS * 8]; // per-(row, ktile) partial min value
__device__ int   g_pminidx[N_ROWS * 8]; // per-(row, ktile) partial argmin
__device__ int   g_idx[N_ROWS];         // final argmin index per row
__device__ float g_counts[KCB];         // cluster sizes (float, like one-hot sum)
__device__ float g_dwT[KCB * DIM];      // dw transposed [K, D]
__device__ float g_loss_sum;            // sum of (q-x)^2
__device__ float g_smoothed[KCB];       // smoothed cluster size
__device__ float g_bias;                // 1 - gamma^counter

__device__ __forceinline__ unsigned long long dup_f32(float v) {
    unsigned int u = __float_as_uint(v);
    return ((unsigned long long)u << 32) | (unsigned long long)u;
}

// ---------------- kernels ---------------------------------------------------

// Zero the accumulators that the scatter pass updates (graph replays!).
__global__ void k_zero() {
    int i = blockIdx.x * 256 + threadIdx.x;   // grid 1024 -> covers KCB*DIM
    if (i < KCB * DIM) g_dwT[i] = 0.0f;
    if (i < KCB)       g_counts[i] = 0.0f;
    if (i == 0)        g_loss_sum = 0.0f;
}

// Transpose codebook [D,K] -> cbT [K,D] (coalesced both sides via smem tile).
__global__ void k_transpose(const float* __restrict__ cb) {
    __shared__ float tile[32][33];
    int k0 = blockIdx.x * 32;
    int d0 = blockIdx.y * 32;
    int x = threadIdx.x, y = threadIdx.y;
    tile[y][x] = cb[(d0 + y) * KCB + (k0 + x)];
    __syncthreads();
    g_cbT[(k0 + y) * DIM + (d0 + x)] = tile[x][y];
}

// Per-code squared norm from cbT (contiguous rows). 1024 blocks x 32 threads.
__global__ void k_cnorm() {
    int k = blockIdx.x, lane = threadIdx.x;
    float s = 0.0f;
#pragma unroll
    for (int i = 0; i < 8; i++) {
        float v = g_cbT[k * DIM + lane + 32 * i];
        s = fmaf(v, v, s);
    }
#pragma unroll
    for (int o = 16; o; o >>= 1) s += __shfl_xor_sync(0xffffffffu, s, o);
    if (lane == 0) g_cnorm[k] = s;
}

// Per-row squared norm. 8192 blocks x 256 threads, one warp per row.
__global__ void k_xnorm(const float* __restrict__ x) {
    int warp = threadIdx.x >> 5, lane = threadIdx.x & 31;
    int r = blockIdx.x * 8 + warp;
    const float* xr = x + (size_t)r * DIM;
    float s = 0.0f;
#pragma unroll
    for (int i = 0; i < 8; i++) {
        float v = xr[lane + 32 * i];
        s = fmaf(v, v, s);
    }
#pragma unroll
    for (int o = 16; o; o >>= 1) s += __shfl_xor_sync(0xffffffffu, s, o);
    if (lane == 0) g_xnorm[r] = s;
}

// Fused SGEMM + per-row partial argmin, packed-f32x2 inner loop.
// Block tile: 128 rows x 128 codes, full D=256 accumulation (32 stages of 8).
// Thread microtile 8 rows x 8 cols (= 8 x 4 f32x2 pairs). Double-buffered smem.
__global__ __launch_bounds__(256, 2) void k_gemm_argmin(
    const float* __restrict__ A,   // flat [N, 256]
    const float* __restrict__ B)   // codebook [256, 1024]
{
    // A tile stored pre-duplicated: each entry holds packed (a, a) as u64.
    __shared__ __align__(16) unsigned long long As2[2][8][130]; // [buf][d][row]
    __shared__ __align__(16) float Bs[2][8][132];               // [buf][d][col]
    __shared__ float redv[128][17];
    __shared__ int   redi[128][17];

    const int r0 = blockIdx.x * 128;
    const int c0 = blockIdx.y * 128;
    const int t  = threadIdx.x;
    const int tx = t & 15, ty = t >> 4;

    // global load mapping
    const int arow  = t >> 1;            // 0..127
    const int acol4 = (t & 1) * 4;       // 0 or 4
    const int brow  = t >> 5;            // 0..7
    const int bcol  = (t & 31) * 4;      // 0..124

    const float* aptr = A + (size_t)(r0 + arow) * DIM + acol4;
    const float* bptr = B + (size_t)brow * KCB + c0 + bcol;

    // stage 0 load
    {
        float4 av = *(const float4*)aptr;
        float4 bv = *(const float4*)bptr;
        As2[0][acol4 + 0][arow] = dup_f32(av.x);
        As2[0][acol4 + 1][arow] = dup_f32(av.y);
        As2[0][acol4 + 2][arow] = dup_f32(av.z);
        As2[0][acol4 + 3][arow] = dup_f32(av.w);
        *(float4*)&Bs[0][brow][bcol] = bv;
    }
    __syncthreads();

    // acc2[i][j2] = packed accumulators for (row i, cols 2*j2 and 2*j2+1)
    unsigned long long acc2[8][4];
#pragma unroll
    for (int i = 0; i < 8; i++)
#pragma unroll
        for (int j = 0; j < 4; j++) acc2[i][j] = 0ull;

#pragma unroll 1
    for (int s = 0; s < 32; s++) {
        const int cur = s & 1;
        float4 av, bv;
        if (s < 31) {
            av = *(const float4*)(aptr + (s + 1) * 8);
            bv = *(const float4*)(bptr + (size_t)(s + 1) * 8 * KCB);
        }
#pragma unroll
        for (int kk = 0; kk < 8; kk++) {
            unsigned long long a2[8], b2[4];
            {
                const ulonglong2* pa = (const ulonglong2*)&As2[cur][kk][ty * 8];
                ulonglong2 v0 = pa[0], v1 = pa[1], v2 = pa[2], v3 = pa[3];
                a2[0] = v0.x; a2[1] = v0.y; a2[2] = v1.x; a2[3] = v1.y;
                a2[4] = v2.x; a2[5] = v2.y; a2[6] = v3.x; a2[7] = v3.y;
                const ulonglong2* pb = (const ulonglong2*)&Bs[cur][kk][tx * 8];
                ulonglong2 w0 = pb[0], w1 = pb[1];
                b2[0] = w0.x; b2[1] = w0.y; b2[2] = w1.x; b2[3] = w1.y;
            }
#pragma unroll
            for (int i = 0; i < 8; i++)
#pragma unroll
                for (int j = 0; j < 4; j++)
                    FMA_F32X2(acc2[i][j], a2[i], b2[j], acc2[i][j]);
        }
        if (s < 31) {
            const int nxt = cur ^ 1;
            As2[nxt][acol4 + 0][arow] = dup_f32(av.x);
            As2[nxt][acol4 + 1][arow] = dup_f32(av.y);
            As2[nxt][acol4 + 2][arow] = dup_f32(av.z);
            As2[nxt][acol4 + 3][arow] = dup_f32(av.w);
            *(float4*)&Bs[nxt][brow][bcol] = bv;
            __syncthreads();
        }
    }

    // Epilogue: distance = (xnorm - 2*dot) + cnorm; per-thread row mins.
    float xn[8], cn[8];
#pragma unroll
    for (int i = 0; i < 8; i++) xn[i] = g_xnorm[r0 + ty * 8 + i];
#pragma unroll
    for (int j = 0; j < 8; j++) cn[j] = g_cnorm[c0 + tx * 8 + j];

#pragma unroll
    for (int i = 0; i < 8; i++) {
        float bvv = 1e30f;
        int   bii = 0;
#pragma unroll
        for (int j = 0; j < 8; j++) {
            unsigned long long p = acc2[i][j >> 1];
            float dot = (j & 1) ? __uint_as_float((unsigned int)(p >> 32))
                                : __uint_as_float((unsigned int)p);
            // 2*dot is exact in fp32, so fma(-2,dot,xn) == (xn - 2*dot) rounding
            float sd = fmaf(-2.0f, dot, xn[i]) + cn[j];
            if (sd < bvv) { bvv = sd; bii = c0 + tx * 8 + j; }  // ascending j
        }
        redv[ty * 8 + i][tx] = bvv;
        redi[ty * 8 + i][tx] = bii;
    }
    __syncthreads();

    if (t < 128) {
        float bvv = redv[t][0];
        int   bii = redi[t][0];
#pragma unroll
        for (int x2 = 1; x2 < 16; x2++) {
            float v = redv[t][x2];
            if (v < bvv) { bvv = v; bii = redi[t][x2]; }  // ascending cols
        }
        g_pminval[(size_t)(r0 + t) * 8 + blockIdx.y] = bvv;
        g_pminidx[(size_t)(r0 + t) * 8 + blockIdx.y] = bii;
    }
}

// Combine 8 k-tile partials per row into the final argmin.
__global__ void k_combine() {
    int r = blockIdx.x * 1024 + threadIdx.x;   // grid 64
    const float* pv = &g_pminval[(size_t)r * 8];
    const int*   pi = &g_pminidx[(size_t)r * 8];
    float bv = pv[0];
    int   bi = pi[0];
#pragma unroll
    for (int j = 1; j < 8; j++) {
        float v = pv[j];
        if (v < bv) { bv = v; bi = pi[j]; }    // ascending tiles: first-min wins
    }
    g_idx[r] = bi;
}

// Per-row pass: ste output, loss sum, counts, dw accumulation.
// 8192 blocks x 256 threads; one warp per row.
__global__ void k_scatter(const float* __restrict__ x, float* __restrict__ out) {
    __shared__ float lsum[8];
    int warp = threadIdx.x >> 5, lane = threadIdx.x & 31;
    int r = blockIdx.x * 8 + warp;
    int k = g_idx[r];
    const float* xr = x + (size_t)r * DIM;
    const float* cr = g_cbT + (size_t)k * DIM;
    float* dw = g_dwT + (size_t)k * DIM;
    float ls = 0.0f;
#pragma unroll
    for (int i = 0; i < 8; i++) {
        int d = lane + 32 * i;
        float xv = xr[d];
        float q  = cr[d];
        float diff = q - xv;                    // matches stop_gradient(q - x)
        out[(size_t)r * DIM + d] = xv + diff;   // ste = x + (q - x), ref rounding
        ls = fmaf(diff, diff, ls);
        atomicAdd(&dw[d], xv);
    }
    if (lane == 0) atomicAdd(&g_counts[k], 1.0f);
#pragma unroll
    for (int o = 16; o; o >>= 1) ls += __shfl_xor_sync(0xffffffffu, ls, o);
    if (lane == 0) lsum[warp] = ls;
    __syncthreads();
    if (threadIdx.x == 0) {
        float s = 0.0f;
#pragma unroll
        for (int w = 0; w < 8; w++) s += lsum[w];
        atomicAdd(&g_loss_sum, s);
    }
}

// Small finalize: smoothed cluster sizes, bias, perplexity, loss scalars.
__global__ void k_finalize(const float* __restrict__ ema_cluster,
                           const int* __restrict__ counter,
                           float* __restrict__ out) {
    __shared__ float red[1024];
    __shared__ float nsh;
    int k = threadIdx.x;
    const float decay = 0.9f, one = 1.0f;
    float bias = one - powf(decay, (float)counter[0]);
    float cs  = g_counts[k];
    float hid = ema_cluster[k] * decay + cs * (one - decay);
    float avg_cs = hid / bias;

    red[k] = avg_cs;
    __syncthreads();
    for (int s2 = 512; s2 > 0; s2 >>= 1) {
        if (k < s2) red[k] += red[k + s2];
        __syncthreads();
    }
    if (k == 0) { nsh = red[0]; g_bias = bias; }
    __syncthreads();
    float n = nsh;
    g_smoothed[k] = (avg_cs + 1e-5f) / (n + 1024.0f * 1e-5f) * n;

    // perplexity
    float p = cs * (1.0f / 65536.0f);           // exact power-of-two scale
    float e = p * logf(p + 1e-10f);
    __syncthreads();
    red[k] = e;
    __syncthreads();
    for (int s2 = 512; s2 > 0; s2 >>= 1) {
        if (k < s2) red[k] += red[k + s2];
        __syncthreads();
    }
    if (k == 0) {
        out[OFF_PERP] = expf(-red[0]);
        out[OFF_LOSS] = 0.25f * (g_loss_sum * (1.0f / 16777216.0f)); // exact scales
    }
}

// new_codebook[d,k] = ((ema_dw*decay + dw*(1-decay))/bias) / smoothed[k]
__global__ void k_cbout(const float* __restrict__ ema_dw, float* __restrict__ out) {
    int d = blockIdx.x;    // 256
    int k = threadIdx.x;   // 1024
    const float decay = 0.9f, one = 1.0f;
    float hid = ema_dw[(size_t)d * KCB + k] * decay
              + g_dwT[(size_t)k * DIM + d] * (one - decay);
    float avg = hid / g_bias;
    out[OFF_CB + (size_t)d * KCB + k] = avg / g_smoothed[k];
}

// ---------------- launch -----------------------------------------------------
extern "C" void kernel_launch(void* const* d_in, const int* in_sizes, int n_in,
                              void* d_out, int out_size) {
    const float* x       = (const float*)d_in[0];  // inputs [64,32,32,256]
    const float* cb      = (const float*)d_in[1];  // codebook [256,1024]
    const float* ema_c   = (const float*)d_in[2];  // ema_hidden_cluster [1024]
    const float* ema_dw  = (const float*)d_in[3];  // ema_hidden_dw [256,1024]
    const int*   counter = (const int*)d_in[4];    // scalar int
    float* out = (float*)d_out;

    k_zero<<<1024, 256>>>();
    k_transpose<<<dim3(KCB / 32, DIM / 32), dim3(32, 32)>>>(cb);
    k_cnorm<<<KCB, 32>>>();
    k_xnorm<<<N_ROWS / 8, 256>>>(x);
    k_gemm_argmin<<<dim3(N_ROWS / 128, KCB / 128), 256>>>(x, cb);
    k_combine<<<N_ROWS / 1024, 1024>>>();
    k_scatter<<<N_ROWS / 8, 256>>>(x, out);
    k_finalize<<<1, 1024>>>(ema_c, counter, out);
    k_cbout<<<DIM, 1024>>>(ema_dw, out);
}

// round 11
// speedup vs baseline: 1.2200x; 1.2200x over previous
#include <cuda_runtime.h>
#include <cuda_bf16.h>
#include <cuda_fp16.h>
#include <cstdint>

// Problem constants
#define N_ROWS 65536   // B*H*W = 64*32*32
#define DIM    256     // D
#define KCB    1024    // K

#define OFF_PERP  16777216
#define OFF_LOSS  16777217
#define OFF_CB    16777218

#define MARGIN 16.0f

__device__ __forceinline__ uint32_t smem_to_u32(const void* smem_ptr) {
    uint32_t addr;
    asm("{ .reg .u64 tmp; cvta.to.shared.u64 tmp, %1; cvt.u32.u64 %0, tmp; }"
        : "=r"(addr) : "l"(smem_ptr));
    return addr;
}

// ---------------- scratch (device globals; no allocation allowed) -----------
__device__ float          g_cbT[KCB * DIM];     // codebook transposed [K, D] fp32
__device__ __nv_bfloat16  g_cbTbf[KCB * DIM];   // codebook transposed bf16
__device__ __nv_bfloat16  g_Abf[(size_t)N_ROWS * DIM];   // inputs bf16 (32MB)
__device__ __half         g_dist[(size_t)N_ROWS * KCB];  // approx distances (128MB)
__device__ float g_cnorm[KCB];
__device__ float g_xnorm[N_ROWS];
__device__ int   g_idx[N_ROWS];
__device__ float g_counts[KCB];
__device__ float g_dwT[KCB * DIM];
__device__ float g_loss_sum;
__device__ float g_smoothed[KCB];
__device__ float g_bias;

// ---------------- small kernels ---------------------------------------------
__global__ void k_zero() {
    int i = blockIdx.x * 256 + threadIdx.x;
    if (i < KCB * DIM) g_dwT[i] = 0.0f;
    if (i < KCB)       g_counts[i] = 0.0f;
    if (i == 0)        g_loss_sum = 0.0f;
}

__global__ void k_transpose(const float* __restrict__ cb) {
    __shared__ float tile[32][33];
    int k0 = blockIdx.x * 32, d0 = blockIdx.y * 32;
    int x = threadIdx.x, y = threadIdx.y;
    tile[y][x] = cb[(d0 + y) * KCB + (k0 + x)];
    __syncthreads();
    g_cbT[(k0 + y) * DIM + (d0 + x)] = tile[x][y];
}

__global__ void k_cnorm() {
    int k = blockIdx.x, lane = threadIdx.x;
    float s = 0.0f;
#pragma unroll
    for (int i = 0; i < 8; i++) {
        float v = g_cbT[k * DIM + lane + 32 * i];
        s = fmaf(v, v, s);
    }
#pragma unroll
    for (int o = 16; o; o >>= 1) s += __shfl_xor_sync(0xffffffffu, s, o);
    if (lane == 0) g_cnorm[k] = s;
}

__global__ void k_xnorm(const float* __restrict__ x) {
    int warp = threadIdx.x >> 5, lane = threadIdx.x & 31;
    int r = blockIdx.x * 8 + warp;
    const float* xr = x + (size_t)r * DIM;
    float s = 0.0f;
#pragma unroll
    for (int i = 0; i < 8; i++) {
        float v = xr[lane + 32 * i];
        s = fmaf(v, v, s);
    }
#pragma unroll
    for (int o = 16; o; o >>= 1) s += __shfl_xor_sync(0xffffffffu, s, o);
    if (lane == 0) g_xnorm[r] = s;
}

// fp32 -> bf16 converters (8 elems/thread, uint4 stores)
__global__ void k_convA(const float* __restrict__ x) {
    size_t i = ((size_t)blockIdx.x * 256 + threadIdx.x) * 8;   // grid 8192
    float4 a = *(const float4*)(x + i);
    float4 b = *(const float4*)(x + i + 4);
    __nv_bfloat162 p0 = __floats2bfloat162_rn(a.x, a.y);
    __nv_bfloat162 p1 = __floats2bfloat162_rn(a.z, a.w);
    __nv_bfloat162 p2 = __floats2bfloat162_rn(b.x, b.y);
    __nv_bfloat162 p3 = __floats2bfloat162_rn(b.z, b.w);
    uint4 o;
    o.x = *(uint32_t*)&p0; o.y = *(uint32_t*)&p1;
    o.z = *(uint32_t*)&p2; o.w = *(uint32_t*)&p3;
    *(uint4*)(g_Abf + i) = o;
}

__global__ void k_convCb() {
    size_t i = ((size_t)blockIdx.x * 256 + threadIdx.x) * 8;   // grid 128
    float4 a = *(const float4*)(g_cbT + i);
    float4 b = *(const float4*)(g_cbT + i + 4);
    __nv_bfloat162 p0 = __floats2bfloat162_rn(a.x, a.y);
    __nv_bfloat162 p1 = __floats2bfloat162_rn(a.z, a.w);
    __nv_bfloat162 p2 = __floats2bfloat162_rn(b.x, b.y);
    __nv_bfloat162 p3 = __floats2bfloat162_rn(b.z, b.w);
    uint4 o;
    o.x = *(uint32_t*)&p0; o.y = *(uint32_t*)&p1;
    o.z = *(uint32_t*)&p2; o.w = *(uint32_t*)&p3;
    *(uint4*)(g_cbTbf + i) = o;
}

// ---------------- HMMA (mma.sync bf16) screening GEMM -----------------------
// CTA tile: M=128 x N=128, full K=256 staged in smem once.
// 8 warps = 4(m) x 2(n); warp tile 32x64; 16 k-steps of m16n8k16.
// Padded smem rows (264 bf16 = 528B): ldmatrix conflict-free.
#define LDA 264
#define GEMM_SMEM (2 * 128 * LDA * 2)   // 135168 bytes

__device__ __forceinline__ void ldsm_x4(uint32_t* r, uint32_t addr) {
    asm volatile("ldmatrix.sync.aligned.m8n8.x4.shared.b16 {%0,%1,%2,%3}, [%4];"
                 : "=r"(r[0]), "=r"(r[1]), "=r"(r[2]), "=r"(r[3]) : "r"(addr));
}

__device__ __forceinline__ void mma_16816(float* c, const uint32_t* a,
                                          uint32_t b0, uint32_t b1) {
    asm volatile(
        "mma.sync.aligned.m16n8k16.row.col.f32.bf16.bf16.f32 "
        "{%0,%1,%2,%3}, {%4,%5,%6,%7}, {%8,%9}, {%0,%1,%2,%3};"
        : "+f"(c[0]), "+f"(c[1]), "+f"(c[2]), "+f"(c[3])
        : "r"(a[0]), "r"(a[1]), "r"(a[2]), "r"(a[3]), "r"(b0), "r"(b1));
}

__global__ __launch_bounds__(256, 1) void k_gemm_hmma() {
    extern __shared__ __nv_bfloat16 sm[];
    __nv_bfloat16* As = sm;                 // [128][264]
    __nv_bfloat16* Bs = sm + 128 * LDA;     // [128][264]

    const int t = threadIdx.x;
    const int lane = t & 31, wid = t >> 5;
    const int warp_m = wid & 3, warp_n = wid >> 2;
    const int r0 = blockIdx.x * 128;
    const int c0 = blockIdx.y * 128;

    // stage tiles (whole K)
    {
        const uint4* a4 = (const uint4*)(g_Abf   + (size_t)r0 * DIM);
        const uint4* b4 = (const uint4*)(g_cbTbf + (size_t)c0 * DIM);
#pragma unroll
        for (int i = t; i < 4096; i += 256) {
            int r = i >> 5, c = i & 31;
            *(uint4*)&As[r * LDA + c * 8] = a4[r * 32 + c];
            *(uint4*)&Bs[r * LDA + c * 8] = b4[r * 32 + c];
        }
    }
    __syncthreads();

    const uint32_t as_u = smem_to_u32(As);
    const uint32_t bs_u = smem_to_u32(Bs);

    // ldmatrix per-lane base addresses
    uint32_t aAddr[2];
#pragma unroll
    for (int mf = 0; mf < 2; mf++) {
        int row = warp_m * 32 + mf * 16 + (lane & 15);
        aAddr[mf] = as_u + (uint32_t)(row * LDA + ((lane >> 4) << 3)) * 2u;
    }
    uint32_t bAddr[4];
#pragma unroll
    for (int g = 0; g < 4; g++) {
        int n = warp_n * 64 + g * 16 + (lane & 7) + ((lane >> 4) << 3);
        int k = ((lane >> 3) & 1) << 3;
        bAddr[g] = bs_u + (uint32_t)(n * LDA + k) * 2u;
    }

    float acc[2][8][4];
#pragma unroll
    for (int mf = 0; mf < 2; mf++)
#pragma unroll
        for (int nf = 0; nf < 8; nf++)
#pragma unroll
            for (int e = 0; e < 4; e++) acc[mf][nf][e] = 0.0f;

#pragma unroll
    for (int kk = 0; kk < 16; kk++) {
        const uint32_t koff = (uint32_t)kk * 32u;   // 16 bf16 = 32 bytes
        uint32_t a[2][4], b[4][4];
        ldsm_x4(a[0], aAddr[0] + koff);
        ldsm_x4(a[1], aAddr[1] + koff);
#pragma unroll
        for (int g = 0; g < 4; g++) ldsm_x4(b[g], bAddr[g] + koff);
#pragma unroll
        for (int mf = 0; mf < 2; mf++)
#pragma unroll
            for (int g = 0; g < 4; g++) {
                mma_16816(acc[mf][g * 2 + 0], a[mf], b[g][0], b[g][1]);
                mma_16816(acc[mf][g * 2 + 1], a[mf], b[g][2], b[g][3]);
            }
    }

    // epilogue: dist = xn - 2*dot + cn, store fp16 pairs (4B aligned)
#pragma unroll
    for (int mf = 0; mf < 2; mf++) {
        int row_lo = r0 + warp_m * 32 + mf * 16 + (lane >> 2);
        int row_hi = row_lo + 8;
        float xn_lo = g_xnorm[row_lo];
        float xn_hi = g_xnorm[row_hi];
        __half* dlo = g_dist + (size_t)row_lo * KCB;
        __half* dhi = g_dist + (size_t)row_hi * KCB;
#pragma unroll
        for (int nf = 0; nf < 8; nf++) {
            int col = c0 + warp_n * 64 + nf * 8 + (lane & 3) * 2;
            float cn0 = g_cnorm[col], cn1 = g_cnorm[col + 1];
            float d00 = fmaf(-2.0f, acc[mf][nf][0], xn_lo) + cn0;
            float d01 = fmaf(-2.0f, acc[mf][nf][1], xn_lo) + cn1;
            float d10 = fmaf(-2.0f, acc[mf][nf][2], xn_hi) + cn0;
            float d11 = fmaf(-2.0f, acc[mf][nf][3], xn_hi) + cn1;
            uint32_t plo = (uint32_t)__half_as_ushort(__float2half_rn(d00))
                         | ((uint32_t)__half_as_ushort(__float2half_rn(d01)) << 16);
            uint32_t phi = (uint32_t)__half_as_ushort(__float2half_rn(d10))
                         | ((uint32_t)__half_as_ushort(__float2half_rn(d11)) << 16);
            *(uint32_t*)(dlo + col) = plo;
            *(uint32_t*)(dhi + col) = phi;
        }
    }
}

// ---------------- exact rescore: candidates within MARGIN of approx min -----
// One warp per row; 8 warps per block.
// IMPORTANT: exact dot uses a SINGLE sequential fp32 FMA chain in ascending d —
// identical rounding to the round-4 fp32 GEMM that matched the reference argmin.
__global__ __launch_bounds__(256) void k_rescore(const float* __restrict__ x) {
    __shared__ float xs[8][DIM];
    int warp = threadIdx.x >> 5, lane = threadIdx.x & 31;
    int r = blockIdx.x * 8 + warp;

    // stage x row (256 floats) into smem
    {
        const float4* xr = (const float4*)(x + (size_t)r * DIM);
        float4 v0 = xr[lane], v1 = xr[lane + 32];
        *(float4*)&xs[warp][lane * 4] = v0;
        *(float4*)&xs[warp][128 + lane * 4] = v1;
    }
    __syncwarp();

    // load d~ row: lane handles codes q*256 + lane*8 + [0,8)
    uint4 dv[4];
    const uint4* drow = (const uint4*)(g_dist + (size_t)r * KCB);
#pragma unroll
    for (int q = 0; q < 4; q++) dv[q] = drow[q * 32 + lane];

    float f[32];
#pragma unroll
    for (int q = 0; q < 4; q++) {
        uint32_t w[4] = {dv[q].x, dv[q].y, dv[q].z, dv[q].w};
#pragma unroll
        for (int u = 0; u < 4; u++) {
            f[q * 8 + u * 2]     = __half2float(__ushort_as_half((unsigned short)(w[u] & 0xffff)));
            f[q * 8 + u * 2 + 1] = __half2float(__ushort_as_half((unsigned short)(w[u] >> 16)));
        }
    }

    float lmin = 1e30f;
#pragma unroll
    for (int j = 0; j < 32; j++) lmin = fminf(lmin, f[j]);
#pragma unroll
    for (int o = 16; o; o >>= 1) lmin = fminf(lmin, __shfl_xor_sync(0xffffffffu, lmin, o));
    float thr = lmin + MARGIN;

    float xn = g_xnorm[r];
    float bestv = 1e30f;
    int   besti = 0x7fffffff;
#pragma unroll 1
    for (int j = 0; j < 32; j++) {
        if (f[j] <= thr) {
            int k = (j >> 3) * 256 + lane * 8 + (j & 7);
            const float* cr = g_cbT + (size_t)k * DIM;
            // single sequential chain, ascending d (matches round-4 ordering)
            float acc = 0.0f;
#pragma unroll
            for (int d = 0; d < DIM; d++)
                acc = fmaf(xs[warp][d], cr[d], acc);
            float dist = fmaf(-2.0f, acc, xn) + g_cnorm[k];
            if (dist < bestv || (dist == bestv && k < besti)) { bestv = dist; besti = k; }
        }
    }
#pragma unroll
    for (int o = 16; o; o >>= 1) {
        float vo = __shfl_xor_sync(0xffffffffu, bestv, o);
        int   io = __shfl_xor_sync(0xffffffffu, besti, o);
        if (vo < bestv || (vo == bestv && io < besti)) { bestv = vo; besti = io; }
    }
    if (lane == 0) g_idx[r] = besti;
}

// ---------------- per-row scatter + scalars ----------------------------------
__global__ void k_scatter(const float* __restrict__ x, float* __restrict__ out) {
    __shared__ float lsum[8];
    int warp = threadIdx.x >> 5, lane = threadIdx.x & 31;
    int r = blockIdx.x * 8 + warp;
    int k = g_idx[r];
    const float* xr = x + (size_t)r * DIM;
    const float* cr = g_cbT + (size_t)k * DIM;
    float* dw = g_dwT + (size_t)k * DIM;
    float ls = 0.0f;
#pragma unroll
    for (int i = 0; i < 8; i++) {
        int d = lane + 32 * i;
        float xv = xr[d];
        float q  = cr[d];
        float diff = q - xv;
        out[(size_t)r * DIM + d] = xv + diff;
        ls = fmaf(diff, diff, ls);
        atomicAdd(&dw[d], xv);
    }
    if (lane == 0) atomicAdd(&g_counts[k], 1.0f);
#pragma unroll
    for (int o = 16; o; o >>= 1) ls += __shfl_xor_sync(0xffffffffu, ls, o);
    if (lane == 0) lsum[warp] = ls;
    __syncthreads();
    if (threadIdx.x == 0) {
        float s = 0.0f;
#pragma unroll
        for (int w = 0; w < 8; w++) s += lsum[w];
        atomicAdd(&g_loss_sum, s);
    }
}

__global__ void k_finalize(const float* __restrict__ ema_cluster,
                           const int* __restrict__ counter,
                           float* __restrict__ out) {
    __shared__ float red[1024];
    __shared__ float nsh;
    int k = threadIdx.x;
    const float decay = 0.9f, one = 1.0f;
    float bias = one - powf(decay, (float)counter[0]);
    float cs  = g_counts[k];
    float hid = ema_cluster[k] * decay + cs * (one - decay);
    float avg_cs = hid / bias;

    red[k] = avg_cs;
    __syncthreads();
    for (int s2 = 512; s2 > 0; s2 >>= 1) {
        if (k < s2) red[k] += red[k + s2];
        __syncthreads();
    }
    if (k == 0) { nsh = red[0]; g_bias = bias; }
    __syncthreads();
    float n = nsh;
    g_smoothed[k] = (avg_cs + 1e-5f) / (n + 1024.0f * 1e-5f) * n;

    float p = cs * (1.0f / 65536.0f);
    float e = p * logf(p + 1e-10f);
    __syncthreads();
    red[k] = e;
    __syncthreads();
    for (int s2 = 512; s2 > 0; s2 >>= 1) {
        if (k < s2) red[k] += red[k + s2];
        __syncthreads();
    }
    if (k == 0) {
        out[OFF_PERP] = expf(-red[0]);
        out[OFF_LOSS] = 0.25f * (g_loss_sum * (1.0f / 16777216.0f));
    }
}

__global__ void k_cbout(const float* __restrict__ ema_dw, float* __restrict__ out) {
    int d = blockIdx.x;
    int k = threadIdx.x;
    const float decay = 0.9f, one = 1.0f;
    float hid = ema_dw[(size_t)d * KCB + k] * decay
              + g_dwT[(size_t)k * DIM + d] * (one - decay);
    float avg = hid / g_bias;
    out[OFF_CB + (size_t)d * KCB + k] = avg / g_smoothed[k];
}

// ---------------- launch -----------------------------------------------------
extern "C" void kernel_launch(void* const* d_in, const int* in_sizes, int n_in,
                              void* d_out, int out_size) {
    const float* x       = (const float*)d_in[0];
    const float* cb      = (const float*)d_in[1];
    const float* ema_c   = (const float*)d_in[2];
    const float* ema_dw  = (const float*)d_in[3];
    const int*   counter = (const int*)d_in[4];
    float* out = (float*)d_out;

    cudaFuncSetAttribute(k_gemm_hmma, cudaFuncAttributeMaxDynamicSharedMemorySize, GEMM_SMEM);

    k_zero<<<1024, 256>>>();
    k_transpose<<<dim3(KCB / 32, DIM / 32), dim3(32, 32)>>>(cb);
    k_convCb<<<128, 256>>>();
    k_cnorm<<<KCB, 32>>>();
    k_convA<<<8192, 256>>>(x);
    k_xnorm<<<N_ROWS / 8, 256>>>(x);
    k_gemm_hmma<<<dim3(N_ROWS / 128, KCB / 128), 256, GEMM_SMEM>>>();
    k_rescore<<<N_ROWS / 8, 256>>>(x);
    k_scatter<<<N_ROWS / 8, 256>>>(x, out);
    k_finalize<<<1, 1024>>>(ema_c, counter, out);
    k_cbout<<<DIM, 1024>>>(ema_dw, out);
}

// round 12
// speedup vs baseline: 1.7996x; 1.4751x over previous
#include <cuda_runtime.h>
#include <cuda_bf16.h>
#include <cuda_fp16.h>
#include <cstdint>

// Problem constants
#define N_ROWS 65536   // B*H*W = 64*32*32
#define DIM    256     // D
#define KCB    1024    // K

#define OFF_PERP  16777216
#define OFF_LOSS  16777217
#define OFF_CB    16777218

#define MARGIN 8.0f

__device__ __forceinline__ uint32_t smem_to_u32(const void* smem_ptr) {
    uint32_t addr;
    asm("{ .reg .u64 tmp; cvta.to.shared.u64 tmp, %1; cvt.u32.u64 %0, tmp; }"
        : "=r"(addr) : "l"(smem_ptr));
    return addr;
}

// ---------------- scratch (device globals; no allocation allowed) -----------
__device__ float          g_cbT[KCB * DIM];     // codebook transposed [K, D] fp32
__device__ __nv_bfloat16  g_cbTbf[KCB * DIM];   // codebook transposed bf16
__device__ __nv_bfloat16  g_Abf[(size_t)N_ROWS * DIM];   // inputs bf16 (32MB)
__device__ __half         g_dist[(size_t)N_ROWS * KCB];  // approx distances (128MB)
__device__ float g_cnorm[KCB];
__device__ float g_xnorm[N_ROWS];
__device__ int   g_idx[N_ROWS];
__device__ float g_counts[KCB];
__device__ float g_dwT[KCB * DIM];
__device__ float g_loss_sum;
__device__ float g_smoothed[KCB];
__device__ float g_bias;

// ---------------- small kernels ---------------------------------------------
__global__ void k_zero() {
    int i = blockIdx.x * 256 + threadIdx.x;
    if (i < KCB * DIM) g_dwT[i] = 0.0f;
    if (i < KCB)       g_counts[i] = 0.0f;
    if (i == 0)        g_loss_sum = 0.0f;
}

__global__ void k_transpose(const float* __restrict__ cb) {
    __shared__ float tile[32][33];
    int k0 = blockIdx.x * 32, d0 = blockIdx.y * 32;
    int x = threadIdx.x, y = threadIdx.y;
    tile[y][x] = cb[(d0 + y) * KCB + (k0 + x)];
    __syncthreads();
    g_cbT[(k0 + y) * DIM + (d0 + x)] = tile[x][y];
}

__global__ void k_cnorm() {
    int k = blockIdx.x, lane = threadIdx.x;
    float s = 0.0f;
#pragma unroll
    for (int i = 0; i < 8; i++) {
        float v = g_cbT[k * DIM + lane + 32 * i];
        s = fmaf(v, v, s);
    }
#pragma unroll
    for (int o = 16; o; o >>= 1) s += __shfl_xor_sync(0xffffffffu, s, o);
    if (lane == 0) g_cnorm[k] = s;
}

__global__ void k_xnorm(const float* __restrict__ x) {
    int warp = threadIdx.x >> 5, lane = threadIdx.x & 31;
    int r = blockIdx.x * 8 + warp;
    const float* xr = x + (size_t)r * DIM;
    float s = 0.0f;
#pragma unroll
    for (int i = 0; i < 8; i++) {
        float v = xr[lane + 32 * i];
        s = fmaf(v, v, s);
    }
#pragma unroll
    for (int o = 16; o; o >>= 1) s += __shfl_xor_sync(0xffffffffu, s, o);
    if (lane == 0) g_xnorm[r] = s;
}

// fp32 -> bf16 converters (8 elems/thread, uint4 stores)
__global__ void k_convA(const float* __restrict__ x) {
    size_t i = ((size_t)blockIdx.x * 256 + threadIdx.x) * 8;   // grid 8192
    float4 a = *(const float4*)(x + i);
    float4 b = *(const float4*)(x + i + 4);
    __nv_bfloat162 p0 = __floats2bfloat162_rn(a.x, a.y);
    __nv_bfloat162 p1 = __floats2bfloat162_rn(a.z, a.w);
    __nv_bfloat162 p2 = __floats2bfloat162_rn(b.x, b.y);
    __nv_bfloat162 p3 = __floats2bfloat162_rn(b.z, b.w);
    uint4 o;
    o.x = *(uint32_t*)&p0; o.y = *(uint32_t*)&p1;
    o.z = *(uint32_t*)&p2; o.w = *(uint32_t*)&p3;
    *(uint4*)(g_Abf + i) = o;
}

__global__ void k_convCb() {
    size_t i = ((size_t)blockIdx.x * 256 + threadIdx.x) * 8;   // grid 128
    float4 a = *(const float4*)(g_cbT + i);
    float4 b = *(const float4*)(g_cbT + i + 4);
    __nv_bfloat162 p0 = __floats2bfloat162_rn(a.x, a.y);
    __nv_bfloat162 p1 = __floats2bfloat162_rn(a.z, a.w);
    __nv_bfloat162 p2 = __floats2bfloat162_rn(b.x, b.y);
    __nv_bfloat162 p3 = __floats2bfloat162_rn(b.z, b.w);
    uint4 o;
    o.x = *(uint32_t*)&p0; o.y = *(uint32_t*)&p1;
    o.z = *(uint32_t*)&p2; o.w = *(uint32_t*)&p3;
    *(uint4*)(g_cbTbf + i) = o;
}

// ---------------- HMMA (mma.sync bf16) screening GEMM, pipelined ------------
// CTA tile: M=128 x N=128. K=256 split into 4 chunks of 64, double-buffered
// via cp.async (depth-2 prefetch). Smem 72KB dynamic -> 2 CTAs/SM.
// 8 warps = 4(m) x 2(n); warp tile 32x64; 4 k-steps of m16n8k16 per chunk.
// Row stride 72 bf16 (144B): ldmatrix conflict-free (36 words mod 32 distinct).
#define KC    64
#define LDA2  72
#define TILE_E (128 * LDA2)                 // elems per tile
#define GEMM_SMEM (4 * TILE_E * 2)          // 2 bufs x (A+B) = 73728 bytes

__device__ __forceinline__ void ldsm_x4(uint32_t* r, uint32_t addr) {
    asm volatile("ldmatrix.sync.aligned.m8n8.x4.shared.b16 {%0,%1,%2,%3}, [%4];"
                 : "=r"(r[0]), "=r"(r[1]), "=r"(r[2]), "=r"(r[3]) : "r"(addr));
}

__device__ __forceinline__ void mma_16816(float* c, const uint32_t* a,
                                          uint32_t b0, uint32_t b1) {
    asm volatile(
        "mma.sync.aligned.m16n8k16.row.col.f32.bf16.bf16.f32 "
        "{%0,%1,%2,%3}, {%4,%5,%6,%7}, {%8,%9}, {%0,%1,%2,%3};"
        : "+f"(c[0]), "+f"(c[1]), "+f"(c[2]), "+f"(c[3])
        : "r"(a[0]), "r"(a[1]), "r"(a[2]), "r"(a[3]), "r"(b0), "r"(b1));
}

__device__ __forceinline__ void cpasync16(uint32_t saddr, const void* gptr) {
    asm volatile("cp.async.cg.shared.global [%0], [%1], 16;"
                 :: "r"(saddr), "l"(gptr));
}
#define CP_COMMIT() asm volatile("cp.async.commit_group;" ::: "memory")
#define CP_WAIT(n)  asm volatile("cp.async.wait_group %0;" :: "n"(n) : "memory")

__global__ __launch_bounds__(256, 2) void k_gemm_hmma() {
    extern __shared__ __nv_bfloat16 sm[];
    const uint32_t sm_u = smem_to_u32(sm);

    const int t = threadIdx.x;
    const int lane = t & 31, wid = t >> 5;
    const int warp_m = wid & 3, warp_n = wid >> 2;
    const int r0 = blockIdx.x * 128;
    const int c0 = blockIdx.y * 128;

    // buffer bases (bytes): [buf][A,B]
    // buf b: A at b*2*TILE_E, B at b*2*TILE_E + TILE_E   (elems)
    const __nv_bfloat16* aG = g_Abf   + (size_t)r0 * DIM;
    const __nv_bfloat16* bG = g_cbTbf + (size_t)c0 * DIM;

    // stage one K-chunk into buffer b via cp.async (8 x 16B per thread)
    auto stage = [&](int chunk, int b) {
        const int kc = chunk * KC;
        uint32_t baseA = sm_u + (uint32_t)(b * 2 * TILE_E) * 2u;
        uint32_t baseB = baseA + (uint32_t)TILE_E * 2u;
#pragma unroll
        for (int i = t; i < 2048; i += 256) {
            int isB = i >> 10;
            int j = i & 1023;
            int row = j >> 3, seg = j & 7;
            const __nv_bfloat16* src =
                (isB ? bG : aG) + (size_t)row * DIM + kc + seg * 8;
            uint32_t dst = (isB ? baseB : baseA)
                         + (uint32_t)(row * LDA2 + seg * 8) * 2u;
            cpasync16(dst, src);
        }
    };

    // fragment offsets within a tile (bytes)
    uint32_t aOff[2];
#pragma unroll
    for (int mf = 0; mf < 2; mf++) {
        int row = warp_m * 32 + mf * 16 + (lane & 15);
        aOff[mf] = (uint32_t)(row * LDA2 + ((lane >> 4) << 3)) * 2u;
    }
    uint32_t bOff[4];
#pragma unroll
    for (int g = 0; g < 4; g++) {
        int n = warp_n * 64 + g * 16 + (lane & 7) + ((lane >> 4) << 3);
        int k = ((lane >> 3) & 1) << 3;
        bOff[g] = (uint32_t)(n * LDA2 + k) * 2u;
    }

    float acc[2][8][4];
#pragma unroll
    for (int mf = 0; mf < 2; mf++)
#pragma unroll
        for (int nf = 0; nf < 8; nf++)
#pragma unroll
            for (int e = 0; e < 4; e++) acc[mf][nf][e] = 0.0f;

    // depth-2 prefetch
    stage(0, 0); CP_COMMIT();
    stage(1, 1); CP_COMMIT();

#pragma unroll
    for (int c = 0; c < 4; c++) {
        const int b = c & 1;
        if (c < 2) { CP_WAIT(1); } else { CP_WAIT(0); }
        __syncthreads();

        uint32_t baseA = sm_u + (uint32_t)(b * 2 * TILE_E) * 2u;
        uint32_t baseB = baseA + (uint32_t)TILE_E * 2u;
#pragma unroll
        for (int kk = 0; kk < 4; kk++) {
            const uint32_t koff = (uint32_t)kk * 32u;   // 16 bf16 = 32B
            uint32_t a[2][4], bfr[4][4];
            ldsm_x4(a[0], baseA + aOff[0] + koff);
            ldsm_x4(a[1], baseA + aOff[1] + koff);
#pragma unroll
            for (int g = 0; g < 4; g++) ldsm_x4(bfr[g], baseB + bOff[g] + koff);
#pragma unroll
            for (int mf = 0; mf < 2; mf++)
#pragma unroll
                for (int g = 0; g < 4; g++) {
                    mma_16816(acc[mf][g * 2 + 0], a[mf], bfr[g][0], bfr[g][1]);
                    mma_16816(acc[mf][g * 2 + 1], a[mf], bfr[g][2], bfr[g][3]);
                }
        }
        __syncthreads();
        if (c + 2 < 4) { stage(c + 2, b); CP_COMMIT(); }
    }

    // epilogue: dist = xn - 2*dot + cn, store fp16 pairs (4B aligned)
#pragma unroll
    for (int mf = 0; mf < 2; mf++) {
        int row_lo = r0 + warp_m * 32 + mf * 16 + (lane >> 2);
        int row_hi = row_lo + 8;
        float xn_lo = g_xnorm[row_lo];
        float xn_hi = g_xnorm[row_hi];
        __half* dlo = g_dist + (size_t)row_lo * KCB;
        __half* dhi = g_dist + (size_t)row_hi * KCB;
#pragma unroll
        for (int nf = 0; nf < 8; nf++) {
            int col = c0 + warp_n * 64 + nf * 8 + (lane & 3) * 2;
            float cn0 = g_cnorm[col], cn1 = g_cnorm[col + 1];
            float d00 = fmaf(-2.0f, acc[mf][nf][0], xn_lo) + cn0;
            float d01 = fmaf(-2.0f, acc[mf][nf][1], xn_lo) + cn1;
            float d10 = fmaf(-2.0f, acc[mf][nf][2], xn_hi) + cn0;
            float d11 = fmaf(-2.0f, acc[mf][nf][3], xn_hi) + cn1;
            uint32_t plo = (uint32_t)__half_as_ushort(__float2half_rn(d00))
                         | ((uint32_t)__half_as_ushort(__float2half_rn(d01)) << 16);
            uint32_t phi = (uint32_t)__half_as_ushort(__float2half_rn(d10))
                         | ((uint32_t)__half_as_ushort(__float2half_rn(d11)) << 16);
            *(uint32_t*)(dlo + col) = plo;
            *(uint32_t*)(dhi + col) = phi;
        }
    }
}

// ---------------- exact rescore: candidates within MARGIN of approx min -----
// One warp per row; 8 warps per block.
// Exact dot uses a SINGLE sequential fp32 FMA chain in ascending d —
// identical rounding to the round-4 fp32 GEMM that matched the reference argmin.
__global__ __launch_bounds__(256) void k_rescore(const float* __restrict__ x) {
    __shared__ float xs[8][DIM];
    int warp = threadIdx.x >> 5, lane = threadIdx.x & 31;
    int r = blockIdx.x * 8 + warp;

    {
        const float4* xr = (const float4*)(x + (size_t)r * DIM);
        float4 v0 = xr[lane], v1 = xr[lane + 32];
        *(float4*)&xs[warp][lane * 4] = v0;
        *(float4*)&xs[warp][128 + lane * 4] = v1;
    }
    __syncwarp();

    uint4 dv[4];
    const uint4* drow = (const uint4*)(g_dist + (size_t)r * KCB);
#pragma unroll
    for (int q = 0; q < 4; q++) dv[q] = drow[q * 32 + lane];

    float f[32];
#pragma unroll
    for (int q = 0; q < 4; q++) {
        uint32_t w[4] = {dv[q].x, dv[q].y, dv[q].z, dv[q].w};
#pragma unroll
        for (int u = 0; u < 4; u++) {
            f[q * 8 + u * 2]     = __half2float(__ushort_as_half((unsigned short)(w[u] & 0xffff)));
            f[q * 8 + u * 2 + 1] = __half2float(__ushort_as_half((unsigned short)(w[u] >> 16)));
        }
    }

    float lmin = 1e30f;
#pragma unroll
    for (int j = 0; j < 32; j++) lmin = fminf(lmin, f[j]);
#pragma unroll
    for (int o = 16; o; o >>= 1) lmin = fminf(lmin, __shfl_xor_sync(0xffffffffu, lmin, o));
    float thr = lmin + MARGIN;

    float xn = g_xnorm[r];
    float bestv = 1e30f;
    int   besti = 0x7fffffff;
#pragma unroll 1
    for (int j = 0; j < 32; j++) {
        if (f[j] <= thr) {
            int k = (j >> 3) * 256 + lane * 8 + (j & 7);
            const float* cr = g_cbT + (size_t)k * DIM;
            float acc = 0.0f;
#pragma unroll
            for (int d = 0; d < DIM; d++)
                acc = fmaf(xs[warp][d], cr[d], acc);
            float dist = fmaf(-2.0f, acc, xn) + g_cnorm[k];
            if (dist < bestv || (dist == bestv && k < besti)) { bestv = dist; besti = k; }
        }
    }
#pragma unroll
    for (int o = 16; o; o >>= 1) {
        float vo = __shfl_xor_sync(0xffffffffu, bestv, o);
        int   io = __shfl_xor_sync(0xffffffffu, besti, o);
        if (vo < bestv || (vo == bestv && io < besti)) { bestv = vo; besti = io; }
    }
    if (lane == 0) g_idx[r] = besti;
}

// ---------------- per-row scatter + scalars ----------------------------------
__global__ void k_scatter(const float* __restrict__ x, float* __restrict__ out) {
    __shared__ float lsum[8];
    int warp = threadIdx.x >> 5, lane = threadIdx.x & 31;
    int r = blockIdx.x * 8 + warp;
    int k = g_idx[r];
    const float* xr = x + (size_t)r * DIM;
    const float* cr = g_cbT + (size_t)k * DIM;
    float* dw = g_dwT + (size_t)k * DIM;
    float ls = 0.0f;
#pragma unroll
    for (int i = 0; i < 8; i++) {
        int d = lane + 32 * i;
        float xv = xr[d];
        float q  = cr[d];
        float diff = q - xv;
        out[(size_t)r * DIM + d] = xv + diff;
        ls = fmaf(diff, diff, ls);
        atomicAdd(&dw[d], xv);
    }
    if (lane == 0) atomicAdd(&g_counts[k], 1.0f);
#pragma unroll
    for (int o = 16; o; o >>= 1) ls += __shfl_xor_sync(0xffffffffu, ls, o);
    if (lane == 0) lsum[warp] = ls;
    __syncthreads();
    if (threadIdx.x == 0) {
        float s = 0.0f;
#pragma unroll
        for (int w = 0; w < 8; w++) s += lsum[w];
        atomicAdd(&g_loss_sum, s);
    }
}

__global__ void k_finalize(const float* __restrict__ ema_cluster,
                           const int* __restrict__ counter,
                           float* __restrict__ out) {
    __shared__ float red[1024];
    __shared__ float nsh;
    int k = threadIdx.x;
    const float decay = 0.9f, one = 1.0f;
    float bias = one - powf(decay, (float)counter[0]);
    float cs  = g_counts[k];
    float hid = ema_cluster[k] * decay + cs * (one - decay);
    float avg_cs = hid / bias;

    red[k] = avg_cs;
    __syncthreads();
    for (int s2 = 512; s2 > 0; s2 >>= 1) {
        if (k < s2) red[k] += red[k + s2];
        __syncthreads();
    }
    if (k == 0) { nsh = red[0]; g_bias = bias; }
    __syncthreads();
    float n = nsh;
    g_smoothed[k] = (avg_cs + 1e-5f) / (n + 1024.0f * 1e-5f) * n;

    float p = cs * (1.0f / 65536.0f);
    float e = p * logf(p + 1e-10f);
    __syncthreads();
    red[k] = e;
    __syncthreads();
    for (int s2 = 512; s2 > 0; s2 >>= 1) {
        if (k < s2) red[k] += red[k + s2];
        __syncthreads();
    }
    if (k == 0) {
        out[OFF_PERP] = expf(-red[0]);
        out[OFF_LOSS] = 0.25f * (g_loss_sum * (1.0f / 16777216.0f));
    }
}

__global__ void k_cbout(const float* __restrict__ ema_dw, float* __restrict__ out) {
    int d = blockIdx.x;
    int k = threadIdx.x;
    const float decay = 0.9f, one = 1.0f;
    float hid = ema_dw[(size_t)d * KCB + k] * decay
              + g_dwT[(size_t)k * DIM + d] * (one - decay);
    float avg = hid / g_bias;
    out[OFF_CB + (size_t)d * KCB + k] = avg / g_smoothed[k];
}

// ---------------- launch -----------------------------------------------------
extern "C" void kernel_launch(void* const* d_in, const int* in_sizes, int n_in,
                              void* d_out, int out_size) {
    const float* x       = (const float*)d_in[0];
    const float* cb      = (const float*)d_in[1];
    const float* ema_c   = (const float*)d_in[2];
    const float* ema_dw  = (const float*)d_in[3];
    const int*   counter = (const int*)d_in[4];
    float* out = (float*)d_out;

    cudaFuncSetAttribute(k_gemm_hmma, cudaFuncAttributeMaxDynamicSharedMemorySize, GEMM_SMEM);

    k_zero<<<1024, 256>>>();
    k_transpose<<<dim3(KCB / 32, DIM / 32), dim3(32, 32)>>>(cb);
    k_convCb<<<128, 256>>>();
    k_cnorm<<<KCB, 32>>>();
    k_convA<<<8192, 256>>>(x);
    k_xnorm<<<N_ROWS / 8, 256>>>(x);
    k_gemm_hmma<<<dim3(N_ROWS / 128, KCB / 128), 256, GEMM_SMEM>>>();
    k_rescore<<<N_ROWS / 8, 256>>>(x);
    k_scatter<<<N_ROWS / 8, 256>>>(x, out);
    k_finalize<<<1, 1024>>>(ema_c, counter, out);
    k_cbout<<<DIM, 1024>>>(ema_dw, out);
}

// round 13
// speedup vs baseline: 1.9374x; 1.0766x over previous
#include <cuda_runtime.h>
#include <cuda_bf16.h>
#include <cuda_fp16.h>
#include <cstdint>

// Problem constants
#define N_ROWS 65536   // B*H*W = 64*32*32
#define DIM    256     // D
#define KCB    1024    // K

#define OFF_PERP  16777216
#define OFF_LOSS  16777217
#define OFF_CB    16777218

#define MARGIN 8.0f

__device__ __forceinline__ uint32_t smem_to_u32(const void* smem_ptr) {
    uint32_t addr;
    asm("{ .reg .u64 tmp; cvta.to.shared.u64 tmp, %1; cvt.u32.u64 %0, tmp; }"
        : "=r"(addr) : "l"(smem_ptr));
    return addr;
}

// ---------------- scratch (device globals; no allocation allowed) -----------
__device__ float          g_cbT[KCB * DIM];     // codebook transposed [K, D] fp32
__device__ __nv_bfloat16  g_cbTbf[KCB * DIM];   // codebook transposed bf16
__device__ __nv_bfloat16  g_Abf[(size_t)N_ROWS * DIM];   // inputs bf16 (32MB)
__device__ __half         g_dist[(size_t)N_ROWS * KCB];  // approx distances (128MB)
__device__ float g_cnorm[KCB];
__device__ float g_xnorm[N_ROWS];
__device__ float g_counts[KCB];
__device__ float g_dwT[KCB * DIM];
__device__ float g_loss_sum;
__device__ float g_smoothed[KCB];
__device__ float g_bias;

// ---------------- small kernels ---------------------------------------------
__global__ void k_zero() {
    int i = blockIdx.x * 256 + threadIdx.x;
    if (i < KCB * DIM) g_dwT[i] = 0.0f;
    if (i < KCB)       g_counts[i] = 0.0f;
    if (i == 0)        g_loss_sum = 0.0f;
}

// Transpose codebook [D,K] -> cbT [K,D], emitting fp32 AND bf16 in one pass.
__global__ void k_transpose(const float* __restrict__ cb) {
    __shared__ float tile[32][33];
    int k0 = blockIdx.x * 32, d0 = blockIdx.y * 32;
    int x = threadIdx.x, y = threadIdx.y;
    tile[y][x] = cb[(d0 + y) * KCB + (k0 + x)];
    __syncthreads();
    float v = tile[x][y];
    g_cbT[(k0 + y) * DIM + (d0 + x)]   = v;
    g_cbTbf[(k0 + y) * DIM + (d0 + x)] = __float2bfloat16_rn(v);
}

__global__ void k_cnorm() {
    int k = blockIdx.x, lane = threadIdx.x;
    float s = 0.0f;
#pragma unroll
    for (int i = 0; i < 8; i++) {
        float v = g_cbT[k * DIM + lane + 32 * i];
        s = fmaf(v, v, s);
    }
#pragma unroll
    for (int o = 16; o; o >>= 1) s += __shfl_xor_sync(0xffffffffu, s, o);
    if (lane == 0) g_cnorm[k] = s;
}

// Fused: read x ONCE per row -> xnorm (identical reduction pattern) + bf16 row.
// One warp per row; 8 warps per block; grid 8192.
__global__ void k_convA_xnorm(const float* __restrict__ x) {
    int warp = threadIdx.x >> 5, lane = threadIdx.x & 31;
    int r = blockIdx.x * 8 + warp;
    const float* xr = x + (size_t)r * DIM;
    float v[8];
    float s = 0.0f;
#pragma unroll
    for (int i = 0; i < 8; i++) {
        v[i] = xr[lane + 32 * i];
        s = fmaf(v[i], v[i], s);
    }
#pragma unroll
    for (int o = 16; o; o >>= 1) s += __shfl_xor_sync(0xffffffffu, s, o);
    if (lane == 0) g_xnorm[r] = s;
    // bf16 row: lane stores elems [lane*8, lane*8+8) gathered via shfl.
    // Simpler: re-load contiguous float4 pairs (L1-hot) and convert.
    const float4* xr4 = (const float4*)xr;
    float4 a = xr4[lane];            // elems lane*4 .. lane*4+3   (first 128)
    float4 b = xr4[lane + 32];       // elems 128+lane*4 ..        (second 128)
    __nv_bfloat162 p0 = __floats2bfloat162_rn(a.x, a.y);
    __nv_bfloat162 p1 = __floats2bfloat162_rn(a.z, a.w);
    __nv_bfloat162 p2 = __floats2bfloat162_rn(b.x, b.y);
    __nv_bfloat162 p3 = __floats2bfloat162_rn(b.z, b.w);
    uint32_t* dst = (uint32_t*)(g_Abf + (size_t)r * DIM);
    dst[lane]      = *(uint32_t*)&p0;
    dst[lane + 32] = *(uint32_t*)&p1;   // careful: interleave mapping below
    // NOTE: mapping must place bf16 elem j at g_Abf[r*DIM + j].
    // a covers elems [4*lane,4*lane+4): p0 -> word 2*lane, p1 -> word 2*lane+1
    // b covers elems [128+4*lane, ...): p2 -> word 64+2*lane, p3 -> word 64+2*lane+1
    dst[2 * lane]     = *(uint32_t*)&p0;
    dst[2 * lane + 1] = *(uint32_t*)&p1;
    dst[64 + 2 * lane]     = *(uint32_t*)&p2;
    dst[64 + 2 * lane + 1] = *(uint32_t*)&p3;
}

// ---------------- HMMA (mma.sync bf16) screening GEMM, pipelined ------------
// CTA tile: M=128 x N=128. K=256 split into 4 chunks of 64, double-buffered
// via cp.async (depth-2 prefetch). Smem 72KB dynamic -> 2 CTAs/SM.
#define KC    64
#define LDA2  72
#define TILE_E (128 * LDA2)
#define GEMM_SMEM (4 * TILE_E * 2)          // 73728 bytes

__device__ __forceinline__ void ldsm_x4(uint32_t* r, uint32_t addr) {
    asm volatile("ldmatrix.sync.aligned.m8n8.x4.shared.b16 {%0,%1,%2,%3}, [%4];"
                 : "=r"(r[0]), "=r"(r[1]), "=r"(r[2]), "=r"(r[3]) : "r"(addr));
}

__device__ __forceinline__ void mma_16816(float* c, const uint32_t* a,
                                          uint32_t b0, uint32_t b1) {
    asm volatile(
        "mma.sync.aligned.m16n8k16.row.col.f32.bf16.bf16.f32 "
        "{%0,%1,%2,%3}, {%4,%5,%6,%7}, {%8,%9}, {%0,%1,%2,%3};"
        : "+f"(c[0]), "+f"(c[1]), "+f"(c[2]), "+f"(c[3])
        : "r"(a[0]), "r"(a[1]), "r"(a[2]), "r"(a[3]), "r"(b0), "r"(b1));
}

__device__ __forceinline__ void cpasync16(uint32_t saddr, const void* gptr) {
    asm volatile("cp.async.cg.shared.global [%0], [%1], 16;"
                 :: "r"(saddr), "l"(gptr));
}
#define CP_COMMIT() asm volatile("cp.async.commit_group;" ::: "memory")
#define CP_WAIT(n)  asm volatile("cp.async.wait_group %0;" :: "n"(n) : "memory")

__global__ __launch_bounds__(256, 2) void k_gemm_hmma() {
    extern __shared__ __nv_bfloat16 sm[];
    const uint32_t sm_u = smem_to_u32(sm);

    const int t = threadIdx.x;
    const int lane = t & 31, wid = t >> 5;
    const int warp_m = wid & 3, warp_n = wid >> 2;
    const int r0 = blockIdx.x * 128;
    const int c0 = blockIdx.y * 128;

    const __nv_bfloat16* aG = g_Abf   + (size_t)r0 * DIM;
    const __nv_bfloat16* bG = g_cbTbf + (size_t)c0 * DIM;

    auto stage = [&](int chunk, int b) {
        const int kc = chunk * KC;
        uint32_t baseA = sm_u + (uint32_t)(b * 2 * TILE_E) * 2u;
        uint32_t baseB = baseA + (uint32_t)TILE_E * 2u;
#pragma unroll
        for (int i = t; i < 2048; i += 256) {
            int isB = i >> 10;
            int j = i & 1023;
            int row = j >> 3, seg = j & 7;
            const __nv_bfloat16* src =
                (isB ? bG : aG) + (size_t)row * DIM + kc + seg * 8;
            uint32_t dst = (isB ? baseB : baseA)
                         + (uint32_t)(row * LDA2 + seg * 8) * 2u;
            cpasync16(dst, src);
        }
    };

    uint32_t aOff[2];
#pragma unroll
    for (int mf = 0; mf < 2; mf++) {
        int row = warp_m * 32 + mf * 16 + (lane & 15);
        aOff[mf] = (uint32_t)(row * LDA2 + ((lane >> 4) << 3)) * 2u;
    }
    uint32_t bOff[4];
#pragma unroll
    for (int g = 0; g < 4; g++) {
        int n = warp_n * 64 + g * 16 + (lane & 7) + ((lane >> 4) << 3);
        int k = ((lane >> 3) & 1) << 3;
        bOff[g] = (uint32_t)(n * LDA2 + k) * 2u;
    }

    float acc[2][8][4];
#pragma unroll
    for (int mf = 0; mf < 2; mf++)
#pragma unroll
        for (int nf = 0; nf < 8; nf++)
#pragma unroll
            for (int e = 0; e < 4; e++) acc[mf][nf][e] = 0.0f;

    stage(0, 0); CP_COMMIT();
    stage(1, 1); CP_COMMIT();

#pragma unroll
    for (int c = 0; c < 4; c++) {
        const int b = c & 1;
        if (c < 2) { CP_WAIT(1); } else { CP_WAIT(0); }
        __syncthreads();

        uint32_t baseA = sm_u + (uint32_t)(b * 2 * TILE_E) * 2u;
        uint32_t baseB = baseA + (uint32_t)TILE_E * 2u;
#pragma unroll
        for (int kk = 0; kk < 4; kk++) {
            const uint32_t koff = (uint32_t)kk * 32u;
            uint32_t a[2][4], bfr[4][4];
            ldsm_x4(a[0], baseA + aOff[0] + koff);
            ldsm_x4(a[1], baseA + aOff[1] + koff);
#pragma unroll
            for (int g = 0; g < 4; g++) ldsm_x4(bfr[g], baseB + bOff[g] + koff);
#pragma unroll
            for (int mf = 0; mf < 2; mf++)
#pragma unroll
                for (int g = 0; g < 4; g++) {
                    mma_16816(acc[mf][g * 2 + 0], a[mf], bfr[g][0], bfr[g][1]);
                    mma_16816(acc[mf][g * 2 + 1], a[mf], bfr[g][2], bfr[g][3]);
                }
        }
        __syncthreads();
        if (c + 2 < 4) { stage(c + 2, b); CP_COMMIT(); }
    }

    // epilogue: dist = xn - 2*dot + cn, store fp16 pairs
#pragma unroll
    for (int mf = 0; mf < 2; mf++) {
        int row_lo = r0 + warp_m * 32 + mf * 16 + (lane >> 2);
        int row_hi = row_lo + 8;
        float xn_lo = g_xnorm[row_lo];
        float xn_hi = g_xnorm[row_hi];
        __half* dlo = g_dist + (size_t)row_lo * KCB;
        __half* dhi = g_dist + (size_t)row_hi * KCB;
#pragma unroll
        for (int nf = 0; nf < 8; nf++) {
            int col = c0 + warp_n * 64 + nf * 8 + (lane & 3) * 2;
            float cn0 = g_cnorm[col], cn1 = g_cnorm[col + 1];
            float d00 = fmaf(-2.0f, acc[mf][nf][0], xn_lo) + cn0;
            float d01 = fmaf(-2.0f, acc[mf][nf][1], xn_lo) + cn1;
            float d10 = fmaf(-2.0f, acc[mf][nf][2], xn_hi) + cn0;
            float d11 = fmaf(-2.0f, acc[mf][nf][3], xn_hi) + cn1;
            uint32_t plo = (uint32_t)__half_as_ushort(__float2half_rn(d00))
                         | ((uint32_t)__half_as_ushort(__float2half_rn(d01)) << 16);
            uint32_t phi = (uint32_t)__half_as_ushort(__float2half_rn(d10))
                         | ((uint32_t)__half_as_ushort(__float2half_rn(d11)) << 16);
            *(uint32_t*)(dlo + col) = plo;
            *(uint32_t*)(dhi + col) = phi;
        }
    }
}

// ---------------- fused rescore + scatter ------------------------------------
// One warp per row. Phase 1: exact argmin over margin candidates (identical
// logic/ordering to the passing round-12 rescore). Phase 2: scatter (ste out,
// loss, counts, dw atomics) using the staged smem row — no extra x pass.
__global__ __launch_bounds__(256) void k_rescore_scatter(
    const float* __restrict__ x, float* __restrict__ out)
{
    __shared__ float xs[8][DIM];
    __shared__ float lsum[8];
    int warp = threadIdx.x >> 5, lane = threadIdx.x & 31;
    int r = blockIdx.x * 8 + warp;

    {
        const float4* xr = (const float4*)(x + (size_t)r * DIM);
        float4 v0 = xr[lane], v1 = xr[lane + 32];
        *(float4*)&xs[warp][lane * 4] = v0;
        *(float4*)&xs[warp][128 + lane * 4] = v1;
    }
    __syncwarp();

    uint4 dv[4];
    const uint4* drow = (const uint4*)(g_dist + (size_t)r * KCB);
#pragma unroll
    for (int q = 0; q < 4; q++) dv[q] = drow[q * 32 + lane];

    float f[32];
#pragma unroll
    for (int q = 0; q < 4; q++) {
        uint32_t w[4] = {dv[q].x, dv[q].y, dv[q].z, dv[q].w};
#pragma unroll
        for (int u = 0; u < 4; u++) {
            f[q * 8 + u * 2]     = __half2float(__ushort_as_half((unsigned short)(w[u] & 0xffff)));
            f[q * 8 + u * 2 + 1] = __half2float(__ushort_as_half((unsigned short)(w[u] >> 16)));
        }
    }

    float lmin = 1e30f;
#pragma unroll
    for (int j = 0; j < 32; j++) lmin = fminf(lmin, f[j]);
#pragma unroll
    for (int o = 16; o; o >>= 1) lmin = fminf(lmin, __shfl_xor_sync(0xffffffffu, lmin, o));
    float thr = lmin + MARGIN;

    float xn = g_xnorm[r];
    float bestv = 1e30f;
    int   besti = 0x7fffffff;
#pragma unroll 1
    for (int j = 0; j < 32; j++) {
        if (f[j] <= thr) {
            int k = (j >> 3) * 256 + lane * 8 + (j & 7);
            const float* cr = g_cbT + (size_t)k * DIM;
            float acc = 0.0f;
#pragma unroll
            for (int d = 0; d < DIM; d++)
                acc = fmaf(xs[warp][d], cr[d], acc);
            float dist = fmaf(-2.0f, acc, xn) + g_cnorm[k];
            if (dist < bestv || (dist == bestv && k < besti)) { bestv = dist; besti = k; }
        }
    }
#pragma unroll
    for (int o = 16; o; o >>= 1) {
        float vo = __shfl_xor_sync(0xffffffffu, bestv, o);
        int   io = __shfl_xor_sync(0xffffffffu, besti, o);
        if (vo < bestv || (vo == bestv && io < besti)) { bestv = vo; besti = io; }
    }
    int k = __shfl_sync(0xffffffffu, besti, 0);

    // ---- scatter phase (same ordering as round-12 k_scatter) ----
    const float* cr = g_cbT + (size_t)k * DIM;
    float* dw = g_dwT + (size_t)k * DIM;
    float ls = 0.0f;
#pragma unroll
    for (int i = 0; i < 8; i++) {
        int d = lane + 32 * i;
        float xv = xs[warp][d];
        float q  = cr[d];
        float diff = q - xv;
        out[(size_t)r * DIM + d] = xv + diff;
        ls = fmaf(diff, diff, ls);
        atomicAdd(&dw[d], xv);
    }
    if (lane == 0) atomicAdd(&g_counts[k], 1.0f);
#pragma unroll
    for (int o = 16; o; o >>= 1) ls += __shfl_xor_sync(0xffffffffu, ls, o);
    if (lane == 0) lsum[warp] = ls;
    __syncthreads();
    if (threadIdx.x == 0) {
        float s = 0.0f;
#pragma unroll
        for (int w = 0; w < 8; w++) s += lsum[w];
        atomicAdd(&g_loss_sum, s);
    }
}

__global__ void k_finalize(const float* __restrict__ ema_cluster,
                           const int* __restrict__ counter,
                           float* __restrict__ out) {
    __shared__ float red[1024];
    __shared__ float nsh;
    int k = threadIdx.x;
    const float decay = 0.9f, one = 1.0f;
    float bias = one - powf(decay, (float)counter[0]);
    float cs  = g_counts[k];
    float hid = ema_cluster[k] * decay + cs * (one - decay);
    float avg_cs = hid / bias;

    red[k] = avg_cs;
    __syncthreads();
    for (int s2 = 512; s2 > 0; s2 >>= 1) {
        if (k < s2) red[k] += red[k + s2];
        __syncthreads();
    }
    if (k == 0) { nsh = red[0]; g_bias = bias; }
    __syncthreads();
    float n = nsh;
    g_smoothed[k] = (avg_cs + 1e-5f) / (n + 1024.0f * 1e-5f) * n;

    float p = cs * (1.0f / 65536.0f);
    float e = p * logf(p + 1e-10f);
    __syncthreads();
    red[k] = e;
    __syncthreads();
    for (int s2 = 512; s2 > 0; s2 >>= 1) {
        if (k < s2) red[k] += red[k + s2];
        __syncthreads();
    }
    if (k == 0) {
        out[OFF_PERP] = expf(-red[0]);
        out[OFF_LOSS] = 0.25f * (g_loss_sum * (1.0f / 16777216.0f));
    }
}

__global__ void k_cbout(const float* __restrict__ ema_dw, float* __restrict__ out) {
    int d = blockIdx.x;
    int k = threadIdx.x;
    const float decay = 0.9f, one = 1.0f;
    float hid = ema_dw[(size_t)d * KCB + k] * decay
              + g_dwT[(size_t)k * DIM + d] * (one - decay);
    float avg = hid / g_bias;
    out[OFF_CB + (size_t)d * KCB + k] = avg / g_smoothed[k];
}

// ---------------- launch -----------------------------------------------------
extern "C" void kernel_launch(void* const* d_in, const int* in_sizes, int n_in,
                              void* d_out, int out_size) {
    const float* x       = (const float*)d_in[0];
    const float* cb      = (const float*)d_in[1];
    const float* ema_c   = (const float*)d_in[2];
    const float* ema_dw  = (const float*)d_in[3];
    const int*   counter = (const int*)d_in[4];
    float* out = (float*)d_out;

    cudaFuncSetAttribute(k_gemm_hmma, cudaFuncAttributeMaxDynamicSharedMemorySize, GEMM_SMEM);

    k_zero<<<1024, 256>>>();
    k_transpose<<<dim3(KCB / 32, DIM / 32), dim3(32, 32)>>>(cb);
    k_cnorm<<<KCB, 32>>>();
    k_convA_xnorm<<<N_ROWS / 8, 256>>>(x);
    k_gemm_hmma<<<dim3(N_ROWS / 128, KCB / 128), 256, GEMM_SMEM>>>();
    k_rescore_scatter<<<N_ROWS / 8, 256>>>(x, out);
    k_finalize<<<1, 1024>>>(ema_c, counter, out);
    k_cbout<<<DIM, 1024>>>(ema_dw, out);
}